// round 6
// baseline (speedup 1.0000x reference)
#include <cuda_runtime.h>
#include <cuda_bf16.h>
#include <math.h>

#define B_    256
#define M_    256
#define A_    33
#define NH_   3
#define NOUT_ 100
#define FIN_  66
#define OBS_  17666
#define D2_   76900      // 100 + 3*256*100
#define H2_   128
#define KSPLIT_ 74
#define KC_   1040
#define NEG_BIG (-9e15f)

// ---------------- scratch ----------------
__device__ __nv_bfloat16 g_Wb[3][(size_t)NH_*B_*M_*104]; // Wh bf16 planes [h][b][j][104]
__device__ float    g_e1[NH_*B_*M_];
__device__ float    g_e2[NH_*B_*M_];
__device__ float    g_mx[NH_*B_*M_];
__device__ float    g_rs[NH_*B_*M_];
__device__ float    g_feats[(size_t)B_*M_*NH_*NOUT_]; // post-elu h'  [b][m][h*100+o]
__device__ float    g_x[B_*D2_];
__device__ float    g_hpart[KSPLIT_*B_*H2_];
__device__ float    g_hidT[H2_*B_];
__device__ int      g_idx[B_*M_];
__device__ unsigned g_adjb[M_*8];

// ---------------- f32x2 helpers ----------------
__device__ __forceinline__ unsigned long long splat2(float x){
    unsigned long long r; asm("mov.b64 %0, {%1,%1};" : "=l"(r) : "f"(x)); return r;
}
__device__ __forceinline__ void fma2(unsigned long long& d, unsigned long long a, unsigned long long b){
    asm("fma.rn.f32x2 %0, %1, %2, %0;" : "+l"(d) : "l"(a), "l"(b));
}
__device__ __forceinline__ void unpk(unsigned long long v, float& a, float& b){
    asm("mov.b64 {%0,%1}, %2;" : "=f"(a), "=f"(b) : "l"(v));
}
__device__ __forceinline__ unsigned s2u(const void* p){
    return (unsigned)__cvta_generic_to_shared(p);
}
__device__ __forceinline__ void lds_v2u64(unsigned p, unsigned long long& a, unsigned long long& b){
    asm("ld.shared.v2.u64 {%0,%1}, [%2];" : "=l"(a), "=l"(b) : "r"(p));
}
__device__ __forceinline__ unsigned long long lds_u64(unsigned p){
    unsigned long long a; asm("ld.shared.b64 %0, [%1];" : "=l"(a) : "r"(p)); return a;
}
__device__ __forceinline__ float4 lds_v4f(unsigned p){
    float4 v; asm("ld.shared.v4.f32 {%0,%1,%2,%3}, [%4];"
                  : "=f"(v.x), "=f"(v.y), "=f"(v.z), "=f"(v.w) : "r"(p));
    return v;
}

// ---------------- cp.async ----------------
__device__ __forceinline__ void cp16(unsigned dst, const void* src){
    asm volatile("cp.async.ca.shared.global [%0], [%1], 16;" :: "r"(dst), "l"(src));
}
__device__ __forceinline__ void cp_commit(){
    asm volatile("cp.async.commit_group;" ::: "memory");
}
template<int N> __device__ __forceinline__ void cp_wait(){
    asm volatile("cp.async.wait_group %0;" :: "n"(N) : "memory");
}

// ---------------- mma.sync helpers ----------------
__device__ __forceinline__ void ldsm4(unsigned* r, unsigned a){
    asm volatile("ldmatrix.sync.aligned.m8n8.x4.shared.b16 {%0,%1,%2,%3}, [%4];"
        : "=r"(r[0]), "=r"(r[1]), "=r"(r[2]), "=r"(r[3]) : "r"(a));
}
__device__ __forceinline__ void ldsm4t(unsigned* r, unsigned a){
    asm volatile("ldmatrix.sync.aligned.m8n8.x4.trans.shared.b16 {%0,%1,%2,%3}, [%4];"
        : "=r"(r[0]), "=r"(r[1]), "=r"(r[2]), "=r"(r[3]) : "r"(a));
}
__device__ __forceinline__ void ldsm2t(unsigned& r0, unsigned& r1, unsigned a){
    asm volatile("ldmatrix.sync.aligned.m8n8.x2.trans.shared.b16 {%0,%1}, [%2];"
        : "=r"(r0), "=r"(r1) : "r"(a));
}
__device__ __forceinline__ void mma16816(float* c, const unsigned* a, unsigned b0, unsigned b1){
    asm volatile("mma.sync.aligned.m16n8k16.row.col.f32.bf16.bf16.f32 "
        "{%0,%1,%2,%3}, {%4,%5,%6,%7}, {%8,%9}, {%0,%1,%2,%3};"
        : "+f"(c[0]), "+f"(c[1]), "+f"(c[2]), "+f"(c[3])
        : "r"(a[0]), "r"(a[1]), "r"(a[2]), "r"(a[3]), "r"(b0), "r"(b1));
}

// bf16 3-way split
__device__ __forceinline__ void bsplit(float v, __nv_bfloat16& h, __nv_bfloat16& m, __nv_bfloat16& l){
    h = __float2bfloat16(v);
    float r = v - __bfloat162float(h);
    m = __float2bfloat16(r);
    float r2 = r - __bfloat162float(m);
    l = __float2bfloat16(r2);
}
__device__ __forceinline__ unsigned pack2(__nv_bfloat16 a, __nv_bfloat16 b){
    __nv_bfloat162 t(a, b);
    return *(unsigned*)&t;
}

// ---------------- k0: adjacency -> bitmask ----------------
__global__ void k0_adjbits(const int* __restrict__ adj){
    int i = blockIdx.x, j = threadIdx.x;
    unsigned m = __ballot_sync(0xffffffffu, adj[i*M_ + j] > 0);
    if ((j & 31) == 0) g_adjb[i*8 + (j >> 5)] = m;
}

// ---------------- k1: Wh (bf16 planes) + e1/e2 ----------------
__global__ __launch_bounds__(256) void k1_wh(const float* __restrict__ obs,
                                             const float* __restrict__ Wg,
                                             const float* __restrict__ ag){
    __shared__ __align__(16) float Ws[FIN_*NOUT_];
    __shared__ __align__(16) float a1s[128], a2s[128];
    int b = blockIdx.x, h = blockIdx.y, m = threadIdx.x;
    for (int i = threadIdx.x; i < FIN_*NOUT_; i += 256) Ws[i] = Wg[h*FIN_*NOUT_ + i];
    if (threadIdx.x < 100)       a1s[threadIdx.x]       = ag[h*200 + threadIdx.x];
    else if (threadIdx.x < 200)  a2s[threadIdx.x - 100] = ag[h*200 + threadIdx.x];

    const float* ob = obs + (size_t)b*OBS_;
    float fr[FIN_];
    fr[0] = ob[770  + m];
    fr[1] = ob[1026 + m];
    {
        const float2* r2 = (const float2*)(ob + 1282 + m*32);
        const float2* i2 = (const float2*)(ob + 9474 + m*32);
        #pragma unroll
        for (int s = 0; s < 16; s++){ float2 v = r2[s]; fr[2 + 2*s] = v.x; fr[3 + 2*s] = v.y; }
        #pragma unroll
        for (int s = 0; s < 16; s++){ float2 v = i2[s]; fr[34 + 2*s] = v.x; fr[35 + 2*s] = v.y; }
    }
    __syncthreads();

    unsigned wsu = s2u(Ws), a1u = s2u(a1s), a2u = s2u(a2s);
    int hb = h*B_ + b;
    size_t rowb = ((size_t)hb*M_ + m)*104;
    unsigned long long e1p = 0ull, e2p = 0ull;
    for (int o = 0; o < NOUT_; o += 4){
        unsigned long long c0 = 0ull, c1 = 0ull;
        unsigned p = wsu + o*4;
        #pragma unroll
        for (int f = 0; f < FIN_; f++){
            unsigned long long w0, w1; lds_v2u64(p + f*400, w0, w1);
            unsigned long long xv = splat2(fr[f]);
            fma2(c0, xv, w0); fma2(c1, xv, w1);
        }
        float f0,f1,f2,f3;
        unpk(c0, f0, f1); unpk(c1, f2, f3);
        __nv_bfloat16 h0,m0,l0,h1,m1,l1,h2,m2,l2,h3,m3,l3;
        bsplit(f0,h0,m0,l0); bsplit(f1,h1,m1,l1);
        bsplit(f2,h2,m2,l2); bsplit(f3,h3,m3,l3);
        uint2 sh; sh.x = pack2(h0,h1); sh.y = pack2(h2,h3);
        uint2 sm; sm.x = pack2(m0,m1); sm.y = pack2(m2,m3);
        uint2 sl; sl.x = pack2(l0,l1); sl.y = pack2(l2,l3);
        *(uint2*)&g_Wb[0][rowb + o] = sh;
        *(uint2*)&g_Wb[1][rowb + o] = sm;
        *(uint2*)&g_Wb[2][rowb + o] = sl;
        fma2(e1p, c0, lds_u64(a1u + o*4));  fma2(e1p, c1, lds_u64(a1u + o*4 + 8));
        fma2(e2p, c0, lds_u64(a2u + o*4));  fma2(e2p, c1, lds_u64(a2u + o*4 + 8));
    }
    uint2 z; z.x = 0u; z.y = 0u;
    *(uint2*)&g_Wb[0][rowb + 100] = z;
    *(uint2*)&g_Wb[1][rowb + 100] = z;
    *(uint2*)&g_Wb[2][rowb + 100] = z;
    { float x, y; unpk(e1p, x, y); g_e1[hb*M_ + m] = x + y;
      unpk(e2p, x, y);             g_e2[hb*M_ + m] = x + y; }
}

// ---------------- k1b: per-column softmax stats ----------------
__global__ __launch_bounds__(256) void k1b_stats(){
    __shared__ float e1s[256];
    __shared__ unsigned adjs[2048];
    int b = blockIdx.x, h = blockIdx.y, tid = threadIdx.x;
    int hb = h*B_ + b;
    e1s[tid] = g_e1[hb*M_ + tid];
    for (int i = tid; i < 2048; i += 256) adjs[i] = g_adjb[i];
    __syncthreads();
    int w5 = tid >> 5, bp = tid & 31;
    float e2v = g_e2[hb*M_ + tid];
    float mx = NEG_BIG;
    for (int i = 0; i < M_; i++){
        float v = e1s[i] + e2v; v = fmaxf(v, 0.01f*v);
        bool on = (adjs[i*8 + w5] >> bp) & 1u;
        mx = fmaxf(mx, on ? v : NEG_BIG);
    }
    float sum = 0.f;
    for (int i = 0; i < M_; i++){
        float v = e1s[i] + e2v; v = fmaxf(v, 0.01f*v);
        bool on = (adjs[i*8 + w5] >> bp) & 1u;
        sum += on ? __expf(v - mx) : 0.f;
    }
    g_mx[hb*M_ + tid] = mx;
    g_rs[hb*M_ + tid] = 1.f / sum;
}

// ---------------- k2m: HMMA attention GEMM (bf16x6), merged-ih, cp.async ----------------
// grid (b, h). 512 threads = 16 warps. Warp (mg = wid>>1, nh = wid&1):
//   rows mg*32..mg*32+31 (two m16 tiles), cols nh? 56..103 : 0..55.
// D[i][o] = sum_j att[i][j]*Wh[j][o], K=256 in 8 chunks of 32, double-buffered B.
#define OFF_A0   0          // att planes [256][40] bf16 (20480 B each)
#define OFF_A1   20480
#define OFF_A2   40960
#define OFF_B    61440      // B buffers [2][3][32][104] bf16 (19968 B per buffer)
#define OFF_E1   101376
#define OFF_E2   102400
#define OFF_MX   103424
#define OFF_RS   104448
#define OFF_ADJ  105472     // 256*8 u32
#define K2M_SMEM 113664

extern __shared__ char smm[];
__global__ __launch_bounds__(512) void k2m(){
    const int b = blockIdx.x, h = blockIdx.y;
    const int tid = threadIdx.x, wid = tid >> 5, lid = tid & 31;
    const int hb = h*B_ + b;
    char* sb = smm;
    unsigned sbu = s2u(smm);

    float*    e1s  = (float*)(sb + OFF_E1);
    float*    e2s  = (float*)(sb + OFF_E2);
    float*    smx  = (float*)(sb + OFF_MX);
    float*    srs  = (float*)(sb + OFF_RS);
    unsigned* adjs = (unsigned*)(sb + OFF_ADJ);

    if (tid < 256){
        e1s[tid] = g_e1[hb*M_ + tid];
        e2s[tid] = g_e2[hb*M_ + tid];
        smx[tid] = g_mx[hb*M_ + tid];
        srs[tid] = g_rs[hb*M_ + tid];
    }
    for (int i = tid; i < 2048; i += 512) adjs[i] = g_adjb[i];

    // prefetch B chunk 0
    {
        const char* src = (const char*)&g_Wb[0][((size_t)hb*M_)*104];
        const size_t plane_stride = (size_t)NH_*B_*M_*104*2;
        for (int idx = tid; idx < 1248; idx += 512){
            int p = idx / 416, e = idx - p*416;
            cp16(sbu + OFF_B + p*6656 + e*16, src + p*plane_stride + e*16);
        }
        cp_commit();
    }
    __syncthreads();   // stats visible

    const int mg = wid >> 1, nh = wid & 1;
    const int colb = nh ? 56 : 0;
    float acc[2][7][4];
    #pragma unroll
    for (int mt = 0; mt < 2; mt++)
        #pragma unroll
        for (int nt = 0; nt < 7; nt++){
            acc[mt][nt][0]=0.f; acc[mt][nt][1]=0.f; acc[mt][nt][2]=0.f; acc[mt][nt][3]=0.f;
        }

    for (int c = 0; c < 8; c++){
        const int j0 = c*32;
        // stage att planes: thread = (il = tid>>1 in 0..255, jb = (tid&1)*16)
        {
            int il = tid >> 1, jb = (tid & 1) * 16;
            float e1v = e1s[il];
            unsigned arow = adjs[il*8 + c];
            #pragma unroll
            for (int q = 0; q < 16; q += 2){
                int jg = j0 + jb + q;
                float t0 = e1v + e2s[jg];   t0 = fmaxf(t0, 0.01f*t0);
                float t1 = e1v + e2s[jg+1]; t1 = fmaxf(t1, 0.01f*t1);
                float a0 = ((arow >> (jb+q))   & 1u) ? __expf(t0 - smx[jg])   * srs[jg]   : 0.f;
                float a1 = ((arow >> (jb+q+1)) & 1u) ? __expf(t1 - smx[jg+1]) * srs[jg+1] : 0.f;
                __nv_bfloat16 h0,mm0,l0,h1,mm1,l1;
                bsplit(a0, h0, mm0, l0); bsplit(a1, h1, mm1, l1);
                unsigned off = (unsigned)(il*40 + jb + q)*2;
                *(unsigned*)(sb + OFF_A0 + off) = pack2(h0, h1);
                *(unsigned*)(sb + OFF_A1 + off) = pack2(mm0, mm1);
                *(unsigned*)(sb + OFF_A2 + off) = pack2(l0, l1);
            }
        }
        // prefetch next B chunk into other buffer
        if (c < 7){
            const char* src = (const char*)&g_Wb[0][((size_t)hb*M_ + (c+1)*32)*104];
            const size_t plane_stride = (size_t)NH_*B_*M_*104*2;
            unsigned dbase = sbu + OFF_B + ((c+1)&1)*19968;
            for (int idx = tid; idx < 1248; idx += 512){
                int p = idx / 416, e = idx - p*416;
                cp16(dbase + p*6656 + e*16, src + p*plane_stride + e*16);
            }
            cp_commit();
            cp_wait<1>();
        } else {
            cp_wait<0>();
        }
        __syncthreads();

        unsigned bufu = sbu + OFF_B + (c&1)*19968;
        #pragma unroll
        for (int ks = 0; ks < 2; ks++){
            unsigned af[3][2][4];
            #pragma unroll
            for (int pa = 0; pa < 3; pa++)
                #pragma unroll
                for (int mt = 0; mt < 2; mt++){
                    unsigned addr = sbu + OFF_A0 + pa*20480
                        + (unsigned)((mg*32 + mt*16 + (lid & 15))*40 + ks*16 + (lid >> 4)*8)*2;
                    ldsm4(af[pa][mt], addr);
                }
            unsigned krow = (unsigned)(ks*16 + (lid & 15))*104;
            #pragma unroll
            for (int pb = 0; pb < 3; pb++){
                const int NPA = 3 - pb;
                unsigned bb = bufu + pb*6656;
                #pragma unroll
                for (int g = 0; g < 3; g++){
                    unsigned r[4];
                    ldsm4t(r, bb + (krow + colb + g*16 + (lid >> 4)*8)*2);
                    #pragma unroll
                    for (int pa = 0; pa < 3; pa++){
                        if (pa < NPA){
                            #pragma unroll
                            for (int mt = 0; mt < 2; mt++){
                                mma16816(acc[mt][2*g],     af[pa][mt], r[0], r[1]);
                                mma16816(acc[mt][2*g + 1], af[pa][mt], r[2], r[3]);
                            }
                        }
                    }
                }
                if (!nh){
                    unsigned r0, r1;
                    ldsm2t(r0, r1, bb + (krow + 48)*2);
                    #pragma unroll
                    for (int pa = 0; pa < 3; pa++){
                        if (pa < NPA){
                            #pragma unroll
                            for (int mt = 0; mt < 2; mt++)
                                mma16816(acc[mt][6], af[pa][mt], r0, r1);
                        }
                    }
                }
            }
        }
        __syncthreads();
    }

    // epilogue: fragments -> elu -> g_feats
    const int NT = nh ? 6 : 7;
    int gr = lid >> 2, tg = lid & 3;
    #pragma unroll
    for (int mt = 0; mt < 2; mt++){
        size_t mrow = (size_t)b*M_ + mg*32 + mt*16 + gr;
        float* d0 = g_feats + mrow*300 + h*100;
        float* d1 = d0 + (size_t)8*300;
        #pragma unroll
        for (int nt = 0; nt < 7; nt++){
            if (nt >= NT) break;
            int n = colb + nt*8 + tg*2;
            if (n < 100){
                float v0 = acc[mt][nt][0]; v0 = v0 > 0.f ? v0 : expm1f(v0);
                float v1 = acc[mt][nt][1]; v1 = v1 > 0.f ? v1 : expm1f(v1);
                float v2 = acc[mt][nt][2]; v2 = v2 > 0.f ? v2 : expm1f(v2);
                float v3 = acc[mt][nt][3]; v3 = v3 > 0.f ? v3 : expm1f(v3);
                float2 p0; p0.x = v0; p0.y = v1;
                float2 p1; p1.x = v2; p1.y = v3;
                *(float2*)(d0 + n) = p0;
                *(float2*)(d1 + n) = p1;
            }
        }
    }
}

// ---------------- k3: LayerNorm(300) + elu -> g_x ----------------
__global__ __launch_bounds__(256) void k3_ln(const float* __restrict__ lnw,
                                             const float* __restrict__ lnb){
    int wid = threadIdx.x >> 5, lane = threadIdx.x & 31;
    int row = blockIdx.x*8 + wid;
    const float* xr = g_feats + (size_t)row*300;
    float v[10]; float s = 0.f;
    #pragma unroll
    for (int i = 0; i < 10; i++){
        int c = lane + i*32;
        v[i] = (c < 300) ? xr[c] : 0.f;
        s += v[i];
    }
    #pragma unroll
    for (int o = 16; o; o >>= 1) s += __shfl_xor_sync(0xffffffffu, s, o);
    float mu = s * (1.f/300.f);
    float q = 0.f;
    #pragma unroll
    for (int i = 0; i < 10; i++){
        int c = lane + i*32;
        if (c < 300){ float d = v[i] - mu; q = fmaf(d, d, q); }
    }
    #pragma unroll
    for (int o = 16; o; o >>= 1) q += __shfl_xor_sync(0xffffffffu, q, o);
    float rsv = rsqrtf(q*(1.f/300.f) + 1e-5f);
    int bb = row >> 8, mm = row & 255;
    float* outp = g_x + (size_t)bb*D2_ + 100 + mm*300;
    #pragma unroll
    for (int i = 0; i < 10; i++){
        int c = lane + i*32;
        if (c < 300){
            float t = (v[i] - mu)*rsv*__ldg(&lnw[c]) + __ldg(&lnb[c]);
            outp[c] = t > 0.f ? t : expm1f(t);
        }
    }
}

// ---------------- k3b: server_feat = relu(ss@W1 + b1), split-k ----------------
__global__ __launch_bounds__(256) void k3b_sfeat(const float* __restrict__ obs,
                                                 const float* __restrict__ W1,
                                                 const float* __restrict__ b1){
    __shared__ float ss[772];
    __shared__ float part[256];
    int b = blockIdx.x, tid = threadIdx.x;
    for (int i = tid; i < 770; i += 256) ss[i] = obs[(size_t)b*OBS_ + i];
    __syncthreads();
    if (tid < 200){
        int o = tid % 100, hf = tid / 100;
        int k0 = hf*385, k1 = k0 + 385;
        float a0=0.f,a1=0.f,a2=0.f,a3=0.f;
        int k = k0;
        for (; k + 4 <= k1; k += 4){
            a0 = fmaf(ss[k],   __ldg(&W1[(k)*100 + o]),   a0);
            a1 = fmaf(ss[k+1], __ldg(&W1[(k+1)*100 + o]), a1);
            a2 = fmaf(ss[k+2], __ldg(&W1[(k+2)*100 + o]), a2);
            a3 = fmaf(ss[k+3], __ldg(&W1[(k+3)*100 + o]), a3);
        }
        for (; k < k1; k++) a0 = fmaf(ss[k], __ldg(&W1[k*100 + o]), a0);
        part[tid] = (a0 + a1) + (a2 + a3);
    }
    __syncthreads();
    if (tid < 100)
        g_x[(size_t)b*D2_ + tid] = fmaxf(part[tid] + part[tid + 100] + b1[tid], 0.f);
}

// ---------------- k4: split-K GEMM x(256x76900)@W2(76900x128), FFMA2 ----------------
__global__ __launch_bounds__(256, 4) void k4_gemm(const float* __restrict__ W2){
    __shared__ __align__(16) float xs[64*36];
    __shared__ __align__(16) float ws[64*128];
    int kz = blockIdx.x, by = blockIdx.y;
    int b0 = by*32;
    int kstart = kz*KC_;
    int kend = min(D2_, kstart + KC_);
    int gb = threadIdx.x >> 5, gn = threadIdx.x & 31;
    unsigned xsu = s2u(xs) + gb*16;
    unsigned wsu = s2u(ws) + gn*16;
    unsigned long long acc[4][2] = {{0ull,0ull},{0ull,0ull},{0ull,0ull},{0ull,0ull}};

    for (int kk = kstart; kk < kend; kk += 64){
        #pragma unroll
        for (int i = 0; i < 8; i++){
            int l = threadIdx.x + i*256;
            int bb = l >> 6, kx = l & 63;
            int kg = kk + kx;
            xs[kx*36 + bb] = (kg < kend) ? g_x[(size_t)(b0 + bb)*D2_ + kg] : 0.f;
        }
        #pragma unroll
        for (int i = 0; i < 32; i++){
            int l = threadIdx.x + i*256;
            int kr = l >> 7, n = l & 127;
            int kg = kk + kr;
            ws[l] = (kg < kend) ? W2[(size_t)kg*H2_ + n] : 0.f;
        }
        __syncthreads();
        #pragma unroll 8
        for (int k = 0; k < 64; k++){
            float4 xv = lds_v4f(xsu + k*144);
            unsigned long long w0, w1; lds_v2u64(wsu + k*512, w0, w1);
            unsigned long long s0 = splat2(xv.x), s1 = splat2(xv.y);
            unsigned long long s2 = splat2(xv.z), s3 = splat2(xv.w);
            fma2(acc[0][0], s0, w0); fma2(acc[0][1], s0, w1);
            fma2(acc[1][0], s1, w0); fma2(acc[1][1], s1, w1);
            fma2(acc[2][0], s2, w0); fma2(acc[2][1], s2, w1);
            fma2(acc[3][0], s3, w0); fma2(acc[3][1], s3, w1);
        }
        __syncthreads();
    }
    int bb0 = gb*4, n0 = gn*4;
    #pragma unroll
    for (int r = 0; r < 4; r++){
        float c0,c1,c2,c3;
        unpk(acc[r][0], c0, c1); unpk(acc[r][1], c2, c3);
        *(float4*)&g_hpart[((size_t)kz*B_ + (b0 + bb0 + r))*H2_ + n0] = make_float4(c0,c1,c2,c3);
    }
}

// ---------------- k4b: fixed-order split-K reduce + bias + relu ----------------
__global__ void k4b_reduce(const float* __restrict__ b2){
    int t = blockIdx.x*blockDim.x + threadIdx.x;
    if (t >= B_*H2_) return;
    int b = t >> 7, n = t & 127;
    float s = 0.f;
    for (int kz = 0; kz < KSPLIT_; kz++) s += g_hpart[((size_t)kz*B_ + b)*H2_ + n];
    g_hidT[n*B_ + b] = fmaxf(s + b2[n], 0.f);
}

// ---------------- k5: logits + gumbel + argmax ----------------
__global__ __launch_bounds__(256) void k5_logits(const float* __restrict__ Wout,
                                                 const float* __restrict__ bout,
                                                 const float* __restrict__ ug){
    __shared__ __align__(16) float Wos[H2_*36];
    __shared__ float bos[A_];
    int mb = blockIdx.x, b = threadIdx.x;
    for (int i = threadIdx.x; i < H2_*36; i += 256){
        int hh = i / 36, aa = i - hh*36;
        Wos[i] = (aa < A_) ? Wout[(size_t)mb*H2_*A_ + hh*A_ + aa] : 0.f;
    }
    if (threadIdx.x < A_) bos[threadIdx.x] = bout[mb*A_ + threadIdx.x];
    __syncthreads();

    unsigned wou = s2u(Wos);
    unsigned long long acc[17];
    #pragma unroll
    for (int p = 0; p < 17; p++) acc[p] = 0ull;
    #pragma unroll 2
    for (int hh = 0; hh < H2_; hh++){
        float hv = g_hidT[hh*B_ + b];
        unsigned long long hs = splat2(hv);
        unsigned base = wou + hh*144;
        #pragma unroll
        for (int q = 0; q < 8; q++){
            unsigned long long w0, w1; lds_v2u64(base + q*16, w0, w1);
            fma2(acc[2*q],   hs, w0);
            fma2(acc[2*q+1], hs, w1);
        }
        fma2(acc[16], hs, lds_u64(base + 128));
    }

    const float* u = ug + ((size_t)b*M_ + mb)*A_;
    float best = -INFINITY; int bi = 0;
    #pragma unroll
    for (int p = 0; p < 17; p++){
        float va, vb; unpk(acc[p], va, vb);
        #pragma unroll
        for (int s = 0; s < 2; s++){
            int a = 2*p + s;
            if (a >= A_) break;
            float x = (s ? vb : va) + bos[a];
            float e = x > 0.f ? x : expm1f(x);
            float l = tanhf(e);
            float uu = fmaxf(__ldg(&u[a]), 1e-10f);
            float g = -logf(-logf(uu));
            float z = l + g;
            if (z > best){ best = z; bi = a; }
        }
    }
    g_idx[b*M_ + mb] = bi;
}

// ---------------- k6: one-hot writer ----------------
__global__ void k6_out(float* __restrict__ out){
    int i = blockIdx.x*blockDim.x + threadIdx.x;
    if (i >= B_*M_*A_) return;
    int b = i / (M_*A_);
    int r = i - b*(M_*A_);
    int m = r / A_;
    int a = r - m*A_;
    out[i] = (a == g_idx[b*M_ + m]) ? 1.f : 0.f;
}

extern "C" void kernel_launch(void* const* d_in, const int* in_sizes, int n_in,
                              void* d_out, int out_size){
    const float* obs  = (const float*)d_in[0];
    const int*   adj  = (const int*)  d_in[1];
    const float* ug   = (const float*)d_in[2];
    const float* Wg   = (const float*)d_in[3];
    const float* ag   = (const float*)d_in[4];
    const float* lnw  = (const float*)d_in[5];
    const float* lnb  = (const float*)d_in[6];
    const float* W1   = (const float*)d_in[7];
    const float* b1   = (const float*)d_in[8];
    const float* W2   = (const float*)d_in[9];
    const float* b2   = (const float*)d_in[10];
    const float* Wout = (const float*)d_in[11];
    const float* bout = (const float*)d_in[12];
    float* out = (float*)d_out;

    k0_adjbits<<<M_, 256>>>(adj);
    k1_wh<<<dim3(B_, NH_), 256>>>(obs, Wg, ag);
    k1b_stats<<<dim3(B_, NH_), 256>>>();

    cudaFuncSetAttribute(k2m, cudaFuncAttributeMaxDynamicSharedMemorySize, K2M_SMEM);
    k2m<<<dim3(B_, NH_), 512, K2M_SMEM>>>();

    k3b_sfeat<<<B_, 256>>>(obs, W1, b1);
    k3_ln<<<(B_*M_)/8, 256>>>(lnw, lnb);
    k4_gemm<<<dim3(KSPLIT_, 8), 256>>>(W2);
    k4b_reduce<<<(B_*H2_ + 255)/256, 256>>>(b2);
    k5_logits<<<M_, 256>>>(Wout, bout, ug);
    k6_out<<<(B_*M_*A_ + 255)/256, 256>>>(out);
}

// round 7
// speedup vs baseline: 1.0689x; 1.0689x over previous
#include <cuda_runtime.h>
#include <cuda_bf16.h>
#include <math.h>

#define B_    256
#define M_    256
#define A_    33
#define NH_   3
#define NOUT_ 100
#define FIN_  66
#define OBS_  17666
#define D2_   76900      // 100 + 3*256*100
#define H2_   128
#define KSPLIT_ 74
#define KC_   1040
#define NEG_BIG (-9e15f)

// ---------------- scratch ----------------
__device__ __nv_bfloat16 g_Wb[3][(size_t)NH_*B_*M_*104]; // Wh bf16 planes [h][b][j][104]
__device__ float    g_e1[NH_*B_*M_];
__device__ float    g_e2[NH_*B_*M_];
__device__ float    g_mx[NH_*B_*M_];
__device__ float    g_rs[NH_*B_*M_];
__device__ float    g_feats[(size_t)B_*M_*NH_*NOUT_]; // post-elu h'  [b][m][h*100+o]
__device__ float    g_x[B_*D2_];
__device__ float    g_hpart[KSPLIT_*B_*H2_];
__device__ float    g_hidT[H2_*B_];
__device__ unsigned g_adjb[M_*8];

// ---------------- f32x2 helpers ----------------
__device__ __forceinline__ unsigned long long splat2(float x){
    unsigned long long r; asm("mov.b64 %0, {%1,%1};" : "=l"(r) : "f"(x)); return r;
}
__device__ __forceinline__ void fma2(unsigned long long& d, unsigned long long a, unsigned long long b){
    asm("fma.rn.f32x2 %0, %1, %2, %0;" : "+l"(d) : "l"(a), "l"(b));
}
__device__ __forceinline__ void unpk(unsigned long long v, float& a, float& b){
    asm("mov.b64 {%0,%1}, %2;" : "=f"(a), "=f"(b) : "l"(v));
}
__device__ __forceinline__ unsigned s2u(const void* p){
    return (unsigned)__cvta_generic_to_shared(p);
}
__device__ __forceinline__ void lds_v2u64(unsigned p, unsigned long long& a, unsigned long long& b){
    asm("ld.shared.v2.u64 {%0,%1}, [%2];" : "=l"(a), "=l"(b) : "r"(p));
}
__device__ __forceinline__ unsigned long long lds_u64(unsigned p){
    unsigned long long a; asm("ld.shared.b64 %0, [%1];" : "=l"(a) : "r"(p)); return a;
}
__device__ __forceinline__ float4 lds_v4f(unsigned p){
    float4 v; asm("ld.shared.v4.f32 {%0,%1,%2,%3}, [%4];"
                  : "=f"(v.x), "=f"(v.y), "=f"(v.z), "=f"(v.w) : "r"(p));
    return v;
}

// ---------------- cp.async ----------------
__device__ __forceinline__ void cp16(unsigned dst, const void* src){
    asm volatile("cp.async.ca.shared.global [%0], [%1], 16;" :: "r"(dst), "l"(src));
}
__device__ __forceinline__ void cp_commit(){
    asm volatile("cp.async.commit_group;" ::: "memory");
}
template<int N> __device__ __forceinline__ void cp_wait(){
    asm volatile("cp.async.wait_group %0;" :: "n"(N) : "memory");
}

// ---------------- mma.sync helpers ----------------
__device__ __forceinline__ void ldsm4(unsigned* r, unsigned a){
    asm volatile("ldmatrix.sync.aligned.m8n8.x4.shared.b16 {%0,%1,%2,%3}, [%4];"
        : "=r"(r[0]), "=r"(r[1]), "=r"(r[2]), "=r"(r[3]) : "r"(a));
}
__device__ __forceinline__ void ldsm4t(unsigned* r, unsigned a){
    asm volatile("ldmatrix.sync.aligned.m8n8.x4.trans.shared.b16 {%0,%1,%2,%3}, [%4];"
        : "=r"(r[0]), "=r"(r[1]), "=r"(r[2]), "=r"(r[3]) : "r"(a));
}
__device__ __forceinline__ void ldsm2t(unsigned& r0, unsigned& r1, unsigned a){
    asm volatile("ldmatrix.sync.aligned.m8n8.x2.trans.shared.b16 {%0,%1}, [%2];"
        : "=r"(r0), "=r"(r1) : "r"(a));
}
__device__ __forceinline__ void mma16816(float* c, const unsigned* a, unsigned b0, unsigned b1){
    asm volatile("mma.sync.aligned.m16n8k16.row.col.f32.bf16.bf16.f32 "
        "{%0,%1,%2,%3}, {%4,%5,%6,%7}, {%8,%9}, {%0,%1,%2,%3};"
        : "+f"(c[0]), "+f"(c[1]), "+f"(c[2]), "+f"(c[3])
        : "r"(a[0]), "r"(a[1]), "r"(a[2]), "r"(a[3]), "r"(b0), "r"(b1));
}

// bf16 3-way split
__device__ __forceinline__ void bsplit(float v, __nv_bfloat16& h, __nv_bfloat16& m, __nv_bfloat16& l){
    h = __float2bfloat16(v);
    float r = v - __bfloat162float(h);
    m = __float2bfloat16(r);
    float r2 = r - __bfloat162float(m);
    l = __float2bfloat16(r2);
}
__device__ __forceinline__ unsigned pack2(__nv_bfloat16 a, __nv_bfloat16 b){
    __nv_bfloat162 t(a, b);
    return *(unsigned*)&t;
}

// ---------------- k0: adjacency -> bitmask ----------------
__global__ void k0_adjbits(const int* __restrict__ adj){
    int i = blockIdx.x, j = threadIdx.x;
    unsigned m = __ballot_sync(0xffffffffu, adj[i*M_ + j] > 0);
    if ((j & 31) == 0) g_adjb[i*8 + (j >> 5)] = m;
}

// ---------------- k1: Wh (bf16 planes) + e1/e2 ----------------
__global__ __launch_bounds__(256) void k1_wh(const float* __restrict__ obs,
                                             const float* __restrict__ Wg,
                                             const float* __restrict__ ag){
    __shared__ __align__(16) float Ws[FIN_*NOUT_];
    __shared__ __align__(16) float a1s[128], a2s[128];
    int b = blockIdx.x, h = blockIdx.y, m = threadIdx.x;
    for (int i = threadIdx.x; i < FIN_*NOUT_; i += 256) Ws[i] = Wg[h*FIN_*NOUT_ + i];
    if (threadIdx.x < 100)       a1s[threadIdx.x]       = ag[h*200 + threadIdx.x];
    else if (threadIdx.x < 200)  a2s[threadIdx.x - 100] = ag[h*200 + threadIdx.x];

    const float* ob = obs + (size_t)b*OBS_;
    float fr[FIN_];
    fr[0] = ob[770  + m];
    fr[1] = ob[1026 + m];
    {
        const float2* r2 = (const float2*)(ob + 1282 + m*32);
        const float2* i2 = (const float2*)(ob + 9474 + m*32);
        #pragma unroll
        for (int s = 0; s < 16; s++){ float2 v = r2[s]; fr[2 + 2*s] = v.x; fr[3 + 2*s] = v.y; }
        #pragma unroll
        for (int s = 0; s < 16; s++){ float2 v = i2[s]; fr[34 + 2*s] = v.x; fr[35 + 2*s] = v.y; }
    }
    __syncthreads();

    unsigned wsu = s2u(Ws), a1u = s2u(a1s), a2u = s2u(a2s);
    int hb = h*B_ + b;
    size_t rowb = ((size_t)hb*M_ + m)*104;
    unsigned long long e1p = 0ull, e2p = 0ull;
    for (int o = 0; o < NOUT_; o += 4){
        unsigned long long c0 = 0ull, c1 = 0ull;
        unsigned p = wsu + o*4;
        #pragma unroll
        for (int f = 0; f < FIN_; f++){
            unsigned long long w0, w1; lds_v2u64(p + f*400, w0, w1);
            unsigned long long xv = splat2(fr[f]);
            fma2(c0, xv, w0); fma2(c1, xv, w1);
        }
        float f0,f1,f2,f3;
        unpk(c0, f0, f1); unpk(c1, f2, f3);
        __nv_bfloat16 h0,m0,l0,h1,m1,l1,h2,m2,l2,h3,m3,l3;
        bsplit(f0,h0,m0,l0); bsplit(f1,h1,m1,l1);
        bsplit(f2,h2,m2,l2); bsplit(f3,h3,m3,l3);
        uint2 sh; sh.x = pack2(h0,h1); sh.y = pack2(h2,h3);
        uint2 sm; sm.x = pack2(m0,m1); sm.y = pack2(m2,m3);
        uint2 sl; sl.x = pack2(l0,l1); sl.y = pack2(l2,l3);
        *(uint2*)&g_Wb[0][rowb + o] = sh;
        *(uint2*)&g_Wb[1][rowb + o] = sm;
        *(uint2*)&g_Wb[2][rowb + o] = sl;
        fma2(e1p, c0, lds_u64(a1u + o*4));  fma2(e1p, c1, lds_u64(a1u + o*4 + 8));
        fma2(e2p, c0, lds_u64(a2u + o*4));  fma2(e2p, c1, lds_u64(a2u + o*4 + 8));
    }
    uint2 z; z.x = 0u; z.y = 0u;
    *(uint2*)&g_Wb[0][rowb + 100] = z;
    *(uint2*)&g_Wb[1][rowb + 100] = z;
    *(uint2*)&g_Wb[2][rowb + 100] = z;
    { float x, y; unpk(e1p, x, y); g_e1[hb*M_ + m] = x + y;
      unpk(e2p, x, y);             g_e2[hb*M_ + m] = x + y; }
}

// ---------------- k1b: per-column softmax stats ----------------
__global__ __launch_bounds__(256) void k1b_stats(){
    __shared__ float e1s[256];
    __shared__ unsigned adjs[2048];
    int b = blockIdx.x, h = blockIdx.y, tid = threadIdx.x;
    int hb = h*B_ + b;
    e1s[tid] = g_e1[hb*M_ + tid];
    for (int i = tid; i < 2048; i += 256) adjs[i] = g_adjb[i];
    __syncthreads();
    int w5 = tid >> 5, bp = tid & 31;
    float e2v = g_e2[hb*M_ + tid];
    float mx = NEG_BIG;
    for (int i = 0; i < M_; i++){
        float v = e1s[i] + e2v; v = fmaxf(v, 0.01f*v);
        bool on = (adjs[i*8 + w5] >> bp) & 1u;
        mx = fmaxf(mx, on ? v : NEG_BIG);
    }
    float sum = 0.f;
    for (int i = 0; i < M_; i++){
        float v = e1s[i] + e2v; v = fmaxf(v, 0.01f*v);
        bool on = (adjs[i*8 + w5] >> bp) & 1u;
        sum += on ? __expf(v - mx) : 0.f;
    }
    g_mx[hb*M_ + tid] = mx;
    g_rs[hb*M_ + tid] = 1.f / sum;
}

// ---------------- k2m: HMMA attention GEMM (bf16x6) ----------------
// grid (b, h, ih). 256 threads = 8 warps. Warp (mg = wid>>1 in 0..3, nh = wid&1):
//   rows ih*128 + mg*32 + {0,16}, cols nh? 56..103 : 0..55.
// 2 blocks/SM (78KB smem) restores cross-block stage/MMA overlap.
#define OFF_A0   0          // att planes [128][40] bf16 (10240 B each)
#define OFF_A1   10240
#define OFF_A2   20480
#define OFF_B    30720      // B buffers [2][3][32][104] bf16 (19968 B per buffer)
#define OFF_E1   70656      // 128 f32
#define OFF_E2   71168      // 256 f32
#define OFF_MX   72192
#define OFF_RS   73216
#define OFF_ADJ  74240      // 128*8 u32
#define K2M_SMEM 78336

extern __shared__ char smm[];
__global__ __launch_bounds__(256, 2) void k2m(){
    const int b = blockIdx.x, h = blockIdx.y, ih = blockIdx.z;
    const int tid = threadIdx.x, wid = tid >> 5, lid = tid & 31;
    const int hb = h*B_ + b;
    char* sb = smm;
    unsigned sbu = s2u(smm);

    float*    e1s  = (float*)(sb + OFF_E1);
    float*    e2s  = (float*)(sb + OFF_E2);
    float*    smx  = (float*)(sb + OFF_MX);
    float*    srs  = (float*)(sb + OFF_RS);
    unsigned* adjs = (unsigned*)(sb + OFF_ADJ);

    if (tid < 128) e1s[tid] = g_e1[hb*M_ + ih*128 + tid];
    e2s[tid] = g_e2[hb*M_ + tid];
    smx[tid] = g_mx[hb*M_ + tid];
    srs[tid] = g_rs[hb*M_ + tid];
    for (int i = tid; i < 1024; i += 256) adjs[i] = g_adjb[ih*1024 + i];

    // prefetch B chunk 0
    {
        const char* src = (const char*)&g_Wb[0][((size_t)hb*M_)*104];
        const size_t plane_stride = (size_t)NH_*B_*M_*104*2;
        for (int idx = tid; idx < 1248; idx += 256){
            int p = idx / 416, e = idx - p*416;
            cp16(sbu + OFF_B + p*6656 + e*16, src + p*plane_stride + e*16);
        }
        cp_commit();
    }
    __syncthreads();   // stats + adj visible

    const int mg = wid >> 1, nh = wid & 1;
    const int colb = nh ? 56 : 0;
    float acc[2][7][4];
    #pragma unroll
    for (int mt = 0; mt < 2; mt++)
        #pragma unroll
        for (int nt = 0; nt < 7; nt++){
            acc[mt][nt][0]=0.f; acc[mt][nt][1]=0.f; acc[mt][nt][2]=0.f; acc[mt][nt][3]=0.f;
        }

    for (int c = 0; c < 8; c++){
        const int j0 = c*32;
        // stage att planes: thread = (il = tid>>1 in 0..127, jb = (tid&1)*16)
        {
            int il = tid >> 1, jb = (tid & 1) * 16;
            float e1v = e1s[il];
            unsigned arow = adjs[il*8 + c];
            #pragma unroll
            for (int q = 0; q < 16; q += 2){
                int jg = j0 + jb + q;
                float t0 = e1v + e2s[jg];   t0 = fmaxf(t0, 0.01f*t0);
                float t1 = e1v + e2s[jg+1]; t1 = fmaxf(t1, 0.01f*t1);
                float a0 = ((arow >> (jb+q))   & 1u) ? __expf(t0 - smx[jg])   * srs[jg]   : 0.f;
                float a1 = ((arow >> (jb+q+1)) & 1u) ? __expf(t1 - smx[jg+1]) * srs[jg+1] : 0.f;
                __nv_bfloat16 h0,mm0,l0,h1,mm1,l1;
                bsplit(a0, h0, mm0, l0); bsplit(a1, h1, mm1, l1);
                unsigned off = (unsigned)(il*40 + jb + q)*2;
                *(unsigned*)(sb + OFF_A0 + off) = pack2(h0, h1);
                *(unsigned*)(sb + OFF_A1 + off) = pack2(mm0, mm1);
                *(unsigned*)(sb + OFF_A2 + off) = pack2(l0, l1);
            }
        }
        // prefetch next B chunk into other buffer
        if (c < 7){
            const char* src = (const char*)&g_Wb[0][((size_t)hb*M_ + (c+1)*32)*104];
            const size_t plane_stride = (size_t)NH_*B_*M_*104*2;
            unsigned dbase = sbu + OFF_B + ((c+1)&1)*19968;
            for (int idx = tid; idx < 1248; idx += 256){
                int p = idx / 416, e = idx - p*416;
                cp16(dbase + p*6656 + e*16, src + p*plane_stride + e*16);
            }
            cp_commit();
            cp_wait<1>();
        } else {
            cp_wait<0>();
        }
        __syncthreads();

        unsigned bufu = sbu + OFF_B + (c&1)*19968;
        #pragma unroll
        for (int ks = 0; ks < 2; ks++){
            unsigned af[3][2][4];
            #pragma unroll
            for (int pa = 0; pa < 3; pa++)
                #pragma unroll
                for (int mt = 0; mt < 2; mt++){
                    unsigned addr = sbu + OFF_A0 + pa*10240
                        + (unsigned)((mg*32 + mt*16 + (lid & 15))*40 + ks*16 + (lid >> 4)*8)*2;
                    ldsm4(af[pa][mt], addr);
                }
            unsigned krow = (unsigned)(ks*16 + (lid & 15))*104;
            #pragma unroll
            for (int pb = 0; pb < 3; pb++){
                const int NPA = 3 - pb;
                unsigned bb = bufu + pb*6656;
                #pragma unroll
                for (int g = 0; g < 3; g++){
                    unsigned r[4];
                    ldsm4t(r, bb + (krow + colb + g*16 + (lid >> 4)*8)*2);
                    #pragma unroll
                    for (int pa = 0; pa < 3; pa++){
                        if (pa < NPA){
                            #pragma unroll
                            for (int mt = 0; mt < 2; mt++){
                                mma16816(acc[mt][2*g],     af[pa][mt], r[0], r[1]);
                                mma16816(acc[mt][2*g + 1], af[pa][mt], r[2], r[3]);
                            }
                        }
                    }
                }
                if (!nh){
                    unsigned r0, r1;
                    ldsm2t(r0, r1, bb + (krow + 48)*2);
                    #pragma unroll
                    for (int pa = 0; pa < 3; pa++){
                        if (pa < NPA){
                            #pragma unroll
                            for (int mt = 0; mt < 2; mt++)
                                mma16816(acc[mt][6], af[pa][mt], r0, r1);
                        }
                    }
                }
            }
        }
        __syncthreads();
    }

    // epilogue: fragments -> elu -> g_feats
    const int NT = nh ? 6 : 7;
    int gr = lid >> 2, tg = lid & 3;
    #pragma unroll
    for (int mt = 0; mt < 2; mt++){
        size_t mrow = (size_t)b*M_ + ih*128 + mg*32 + mt*16 + gr;
        float* d0 = g_feats + mrow*300 + h*100;
        float* d1 = d0 + (size_t)8*300;
        #pragma unroll
        for (int nt = 0; nt < 7; nt++){
            if (nt >= NT) break;
            int n = colb + nt*8 + tg*2;
            if (n < 100){
                float v0 = acc[mt][nt][0]; v0 = v0 > 0.f ? v0 : expm1f(v0);
                float v1 = acc[mt][nt][1]; v1 = v1 > 0.f ? v1 : expm1f(v1);
                float v2 = acc[mt][nt][2]; v2 = v2 > 0.f ? v2 : expm1f(v2);
                float v3 = acc[mt][nt][3]; v3 = v3 > 0.f ? v3 : expm1f(v3);
                float2 p0; p0.x = v0; p0.y = v1;
                float2 p1; p1.x = v2; p1.y = v3;
                *(float2*)(d0 + n) = p0;
                *(float2*)(d1 + n) = p1;
            }
        }
    }
}

// ---------------- k3: LayerNorm(300) + elu -> g_x ----------------
__global__ __launch_bounds__(256) void k3_ln(const float* __restrict__ lnw,
                                             const float* __restrict__ lnb){
    int wid = threadIdx.x >> 5, lane = threadIdx.x & 31;
    int row = blockIdx.x*8 + wid;
    const float* xr = g_feats + (size_t)row*300;
    float v[10]; float s = 0.f;
    #pragma unroll
    for (int i = 0; i < 10; i++){
        int c = lane + i*32;
        v[i] = (c < 300) ? xr[c] : 0.f;
        s += v[i];
    }
    #pragma unroll
    for (int o = 16; o; o >>= 1) s += __shfl_xor_sync(0xffffffffu, s, o);
    float mu = s * (1.f/300.f);
    float q = 0.f;
    #pragma unroll
    for (int i = 0; i < 10; i++){
        int c = lane + i*32;
        if (c < 300){ float d = v[i] - mu; q = fmaf(d, d, q); }
    }
    #pragma unroll
    for (int o = 16; o; o >>= 1) q += __shfl_xor_sync(0xffffffffu, q, o);
    float rsv = rsqrtf(q*(1.f/300.f) + 1e-5f);
    int bb = row >> 8, mm = row & 255;
    float* outp = g_x + (size_t)bb*D2_ + 100 + mm*300;
    #pragma unroll
    for (int i = 0; i < 10; i++){
        int c = lane + i*32;
        if (c < 300){
            float t = (v[i] - mu)*rsv*__ldg(&lnw[c]) + __ldg(&lnb[c]);
            outp[c] = t > 0.f ? t : expm1f(t);
        }
    }
}

// ---------------- k3b: server_feat = relu(ss@W1 + b1), split-k ----------------
__global__ __launch_bounds__(256) void k3b_sfeat(const float* __restrict__ obs,
                                                 const float* __restrict__ W1,
                                                 const float* __restrict__ b1){
    __shared__ float ss[772];
    __shared__ float part[256];
    int b = blockIdx.x, tid = threadIdx.x;
    for (int i = tid; i < 770; i += 256) ss[i] = obs[(size_t)b*OBS_ + i];
    __syncthreads();
    if (tid < 200){
        int o = tid % 100, hf = tid / 100;
        int k0 = hf*385, k1 = k0 + 385;
        float a0=0.f,a1=0.f,a2=0.f,a3=0.f;
        int k = k0;
        for (; k + 4 <= k1; k += 4){
            a0 = fmaf(ss[k],   __ldg(&W1[(k)*100 + o]),   a0);
            a1 = fmaf(ss[k+1], __ldg(&W1[(k+1)*100 + o]), a1);
            a2 = fmaf(ss[k+2], __ldg(&W1[(k+2)*100 + o]), a2);
            a3 = fmaf(ss[k+3], __ldg(&W1[(k+3)*100 + o]), a3);
        }
        for (; k < k1; k++) a0 = fmaf(ss[k], __ldg(&W1[k*100 + o]), a0);
        part[tid] = (a0 + a1) + (a2 + a3);
    }
    __syncthreads();
    if (tid < 100)
        g_x[(size_t)b*D2_ + tid] = fmaxf(part[tid] + part[tid + 100] + b1[tid], 0.f);
}

// ---------------- k4: split-K GEMM x(256x76900)@W2(76900x128), FFMA2 ----------------
__global__ __launch_bounds__(256, 4) void k4_gemm(const float* __restrict__ W2){
    __shared__ __align__(16) float xs[64*36];
    __shared__ __align__(16) float ws[64*128];
    int kz = blockIdx.x, by = blockIdx.y;
    int b0 = by*32;
    int kstart = kz*KC_;
    int kend = min(D2_, kstart + KC_);
    int gb = threadIdx.x >> 5, gn = threadIdx.x & 31;
    unsigned xsu = s2u(xs) + gb*16;
    unsigned wsu = s2u(ws) + gn*16;
    unsigned long long acc[4][2] = {{0ull,0ull},{0ull,0ull},{0ull,0ull},{0ull,0ull}};

    for (int kk = kstart; kk < kend; kk += 64){
        #pragma unroll
        for (int i = 0; i < 8; i++){
            int l = threadIdx.x + i*256;
            int bb = l >> 6, kx = l & 63;
            int kg = kk + kx;
            xs[kx*36 + bb] = (kg < kend) ? g_x[(size_t)(b0 + bb)*D2_ + kg] : 0.f;
        }
        #pragma unroll
        for (int i = 0; i < 32; i++){
            int l = threadIdx.x + i*256;
            int kr = l >> 7, n = l & 127;
            int kg = kk + kr;
            ws[l] = (kg < kend) ? W2[(size_t)kg*H2_ + n] : 0.f;
        }
        __syncthreads();
        #pragma unroll 8
        for (int k = 0; k < 64; k++){
            float4 xv = lds_v4f(xsu + k*144);
            unsigned long long w0, w1; lds_v2u64(wsu + k*512, w0, w1);
            unsigned long long s0 = splat2(xv.x), s1 = splat2(xv.y);
            unsigned long long s2 = splat2(xv.z), s3 = splat2(xv.w);
            fma2(acc[0][0], s0, w0); fma2(acc[0][1], s0, w1);
            fma2(acc[1][0], s1, w0); fma2(acc[1][1], s1, w1);
            fma2(acc[2][0], s2, w0); fma2(acc[2][1], s2, w1);
            fma2(acc[3][0], s3, w0); fma2(acc[3][1], s3, w1);
        }
        __syncthreads();
    }
    int bb0 = gb*4, n0 = gn*4;
    #pragma unroll
    for (int r = 0; r < 4; r++){
        float c0,c1,c2,c3;
        unpk(acc[r][0], c0, c1); unpk(acc[r][1], c2, c3);
        *(float4*)&g_hpart[((size_t)kz*B_ + (b0 + bb0 + r))*H2_ + n0] = make_float4(c0,c1,c2,c3);
    }
}

// ---------------- k4b: fixed-order split-K reduce + bias + relu ----------------
__global__ void k4b_reduce(const float* __restrict__ b2){
    int t = blockIdx.x*blockDim.x + threadIdx.x;
    if (t >= B_*H2_) return;
    int b = t >> 7, n = t & 127;
    float s = 0.f;
    for (int kz = 0; kz < KSPLIT_; kz++) s += g_hpart[((size_t)kz*B_ + b)*H2_ + n];
    g_hidT[n*B_ + b] = fmaxf(s + b2[n], 0.f);
}

// ---------------- k5: logits + gumbel + argmax + one-hot write ----------------
__global__ __launch_bounds__(256) void k5_logits(const float* __restrict__ Wout,
                                                 const float* __restrict__ bout,
                                                 const float* __restrict__ ug,
                                                 float* __restrict__ out){
    __shared__ __align__(16) float Wos[H2_*36];
    __shared__ float bos[A_];
    int mb = blockIdx.x, b = threadIdx.x;
    for (int i = threadIdx.x; i < H2_*36; i += 256){
        int hh = i / 36, aa = i - hh*36;
        Wos[i] = (aa < A_) ? Wout[(size_t)mb*H2_*A_ + hh*A_ + aa] : 0.f;
    }
    if (threadIdx.x < A_) bos[threadIdx.x] = bout[mb*A_ + threadIdx.x];
    __syncthreads();

    unsigned wou = s2u(Wos);
    unsigned long long acc[17];
    #pragma unroll
    for (int p = 0; p < 17; p++) acc[p] = 0ull;
    #pragma unroll 2
    for (int hh = 0; hh < H2_; hh++){
        float hv = g_hidT[hh*B_ + b];
        unsigned long long hs = splat2(hv);
        unsigned base = wou + hh*144;
        #pragma unroll
        for (int q = 0; q < 8; q++){
            unsigned long long w0, w1; lds_v2u64(base + q*16, w0, w1);
            fma2(acc[2*q],   hs, w0);
            fma2(acc[2*q+1], hs, w1);
        }
        fma2(acc[16], hs, lds_u64(base + 128));
    }

    const float* u = ug + ((size_t)b*M_ + mb)*A_;
    float best = -INFINITY; int bi = 0;
    #pragma unroll
    for (int p = 0; p < 17; p++){
        float va, vb; unpk(acc[p], va, vb);
        #pragma unroll
        for (int s = 0; s < 2; s++){
            int a = 2*p + s;
            if (a >= A_) break;
            float x = (s ? vb : va) + bos[a];
            float e = x > 0.f ? x : expm1f(x);
            float l = tanhf(e);
            float uu = fmaxf(__ldg(&u[a]), 1e-10f);
            float g = -logf(-logf(uu));
            float z = l + g;
            if (z > best){ best = z; bi = a; }
        }
    }
    // write one-hot row directly (y_hard + y_soft - y_soft == y_hard exactly)
    float* orow = out + ((size_t)b*M_ + mb)*A_;
    #pragma unroll
    for (int a = 0; a < A_; a++) orow[a] = (a == bi) ? 1.f : 0.f;
}

extern "C" void kernel_launch(void* const* d_in, const int* in_sizes, int n_in,
                              void* d_out, int out_size){
    const float* obs  = (const float*)d_in[0];
    const int*   adj  = (const int*)  d_in[1];
    const float* ug   = (const float*)d_in[2];
    const float* Wg   = (const float*)d_in[3];
    const float* ag   = (const float*)d_in[4];
    const float* lnw  = (const float*)d_in[5];
    const float* lnb  = (const float*)d_in[6];
    const float* W1   = (const float*)d_in[7];
    const float* b1   = (const float*)d_in[8];
    const float* W2   = (const float*)d_in[9];
    const float* b2   = (const float*)d_in[10];
    const float* Wout = (const float*)d_in[11];
    const float* bout = (const float*)d_in[12];
    float* out = (float*)d_out;

    k0_adjbits<<<M_, 256>>>(adj);
    k1_wh<<<dim3(B_, NH_), 256>>>(obs, Wg, ag);
    k1b_stats<<<dim3(B_, NH_), 256>>>();

    cudaFuncSetAttribute(k2m, cudaFuncAttributeMaxDynamicSharedMemorySize, K2M_SMEM);
    k2m<<<dim3(B_, NH_, 2), 256, K2M_SMEM>>>();

    k3b_sfeat<<<B_, 256>>>(obs, W1, b1);
    k3_ln<<<(B_*M_)/8, 256>>>(lnw, lnb);
    k4_gemm<<<dim3(KSPLIT_, 8), 256>>>(W2);
    k4b_reduce<<<(B_*H2_ + 255)/256, 256>>>(b2);
    k5_logits<<<M_, 256>>>(Wout, bout, ug, out);
}